// round 4
// baseline (speedup 1.0000x reference)
#include <cuda_runtime.h>
#include <cuda_bf16.h>

// Problem constants (fixed by the reference): N=512, B=256, F=400, D=14, K=2
#define NN 512
#define BB 256
#define FF 400
#define DD 14
#define KK 2
#define PIX (DD * DD)                 // 196 pixels per (b,f)
#define NTILES (BB * FF)              // 102400 (b,f) tiles
#define NWARPS (NTILES / 2)           // 2 tiles per warp -> 51200 warps
#define LOG2E 1.4426950408889634074f
#define INV2PI 0.15915494309189533577f

// Guaranteed single-MUFU ops regardless of harness compile flags.
__device__ __forceinline__ float ex2f_fast(float x) {
    float r; asm("ex2.approx.ftz.f32 %0, %1;" : "=f"(r) : "f"(x)); return r;
}
__device__ __forceinline__ float rcpf_fast(float x) {
    float r; asm("rcp.approx.ftz.f32 %0, %1;" : "=f"(r) : "f"(x)); return r;
}

// Warp layout: lanes 0-15 -> tile (2w), lanes 16-31 -> tile (2w+1).
//   sub = lane & 15.  Lane `sub` (sub<14) owns column pair j0=2*(sub%7), j0+1
//   of rows {2*it + (sub>=7)}, it=0..6.  No shuffles: the x-axis Gaussian
//   factor follows a multiplicative recurrence over the row stride of 2:
//     g(r+2) = g(r)*m(r),  m(r+2) = m(r)*s,  s = exp2(8a)  (a includes log2e).
//   Spot coefficient mask*h/(2*pi*w^2) is folded into g's initial value,
//   so masked spots (c=0) contribute exactly 0 at every row.
__global__ __launch_bounds__(256) void gaussian_spot_kernel(
    const int*          __restrict__ batch_idx,   // (B,)
    const uint2*        __restrict__ m_mask,      // (B,F,K) 32-bit words; nonzero == true
    const float2*       __restrict__ height,      // (B,F,K)
    const float2*       __restrict__ width,       // (B,F,K)
    const float2*       __restrict__ x0,          // (B,F,K)
    const float2*       __restrict__ y0,          // (B,F,K)
    const float*        __restrict__ background,  // (B,F)
    const float2*       __restrict__ target_locs, // (N,F,2)
    float*              __restrict__ out)         // (B,F,D,D)
{
    const int warp  = (blockIdx.x * blockDim.x + threadIdx.x) >> 5;
    const int lane  = threadIdx.x & 31;
    const int sub   = lane & 15;
    const int half  = lane >> 4;

    const int bf = warp * 2 + half;            // this lane's tile (grid is exact)
    const int b  = bf / FF;
    const int f  = bf - b * FF;

    // ---- per-tile parameters (uniform within each half-warp) ----
    const int    n   = batch_idx[b];
    const float2 tl  = target_locs[n * FF + f];
    const float  bg  = background[bf];

    const uint2  mm = m_mask[bf];
    const float2 hh = height[bf];
    const float2 ww = width[bf];
    const float2 xx = x0[bf];
    const float2 yy = y0[bf];

    // spot 0
    const float h0   = (mm.x != 0u) ? hh.x : 0.0f;
    const float iw20 = rcpf_fast(ww.x * ww.x);
    const float a0   = (-0.5f * LOG2E) * iw20;        // exp2-scaled exponent coeff
    const float c0   = h0 * iw20 * INV2PI;
    const float cx0  = tl.x + xx.x;
    const float cy0  = tl.y + yy.x;
    // spot 1
    const float h1   = (mm.y != 0u) ? hh.y : 0.0f;
    const float iw21 = rcpf_fast(ww.y * ww.y);
    const float a1   = (-0.5f * LOG2E) * iw21;
    const float c1   = h1 * iw21 * INV2PI;
    const float cx1  = tl.x + xx.y;
    const float cy1  = tl.y + yy.y;

    // ---- per-lane geometry ----
    const int  r2  = (sub >= 7) ? 1 : 0;       // row parity within the 2-row group
    const int  s7  = sub - 7 * r2;             // column-pair index 0..6 (lanes 14,15 alias 7,8)

    // ---- x-axis recurrence state (rows r2, r2+2, ..., r2+12) ----
    const float d0  = (float)r2 - cx0;
    const float d1  = (float)r2 - cx1;
    float g0 = c0 * ex2f_fast(a0 * d0 * d0);   // coeff folded in
    float m0 = ex2f_fast(a0 * (4.0f * d0 + 4.0f));
    const float sA = ex2f_fast(8.0f * a0);
    float g1 = c1 * ex2f_fast(a1 * d1 * d1);
    float m1 = ex2f_fast(a1 * (4.0f * d1 + 4.0f));
    const float sB = ex2f_fast(8.0f * a1);

    // ---- y entries for columns 2*s7, 2*s7+1 (fixed per lane) ----
    const float py0 = (float)(2 * s7);
    const float py1 = py0 + 1.0f;
    const float e00 = py0 - cy0, e01 = py1 - cy0;
    const float e10 = py0 - cy1, e11 = py1 - cy1;
    const float ya_e = ex2f_fast(a0 * e00 * e00);
    const float ya_o = ex2f_fast(a0 * e01 * e01);
    const float yb_e = ex2f_fast(a1 * e10 * e10);
    const float yb_o = ex2f_fast(a1 * e11 * e11);

    // ---- 7 iterations x (2 rows, float2 columns); no shuffles ----
    float2* o = (float2*)(out + (size_t)bf * PIX + r2 * DD + 2 * s7);
    const bool active = (sub < DD);            // lanes 14,15 are spares

#pragma unroll
    for (int it = 0; it < 7; ++it) {
        float2 v;
        v.x = fmaf(g0, ya_e, fmaf(g1, yb_e, bg));
        v.y = fmaf(g0, ya_o, fmaf(g1, yb_o, bg));
        if (active) __stcs(&o[it * DD], v);    // streaming store, advance 2 rows
        g0 *= m0;  m0 *= sA;                   // row += 2
        g1 *= m1;  m1 *= sB;
    }
}

extern "C" void kernel_launch(void* const* d_in, const int* in_sizes, int n_in,
                              void* d_out, int out_size) {
    (void)in_sizes; (void)n_in; (void)out_size;
    const int*    batch_idx   = (const int*)d_in[0];
    const uint2*  m_mask      = (const uint2*)d_in[1];
    const float2* height      = (const float2*)d_in[2];
    const float2* width       = (const float2*)d_in[3];
    const float2* x0          = (const float2*)d_in[4];
    const float2* y0          = (const float2*)d_in[5];
    const float*  background  = (const float*)d_in[6];
    const float2* target_locs = (const float2*)d_in[7];
    // d_in[8] = pixel_pos (meshgrid) — implicit in the kernel, unused.
    float* out = (float*)d_out;

    const int threads = 256;                      // 8 warps/block, 16 tiles/block
    const int blocks  = (NWARPS * 32) / threads;  // 6400, exact
    gaussian_spot_kernel<<<blocks, threads>>>(batch_idx, m_mask, height, width,
                                              x0, y0, background, target_locs, out);
}